// round 10
// baseline (speedup 1.0000x reference)
#include <cuda_runtime.h>
#include <cuda_fp16.h>
#include <math.h>
#include <string.h>

#define HH 512
#define WW 512
#define NVIEW 768
#define NDCT 736
#define NT 725

// half2 image: g_himg[y*W+x] = (ch0, ch1). 512KB static, aligned for pitch2D.
__device__ __align__(512) __half2 g_himg[HH * WW];

__global__ void build_htex(const float* __restrict__ in) {
    int i = blockIdx.x * blockDim.x + threadIdx.x;
    if (i < HH * WW)
        g_himg[i] = __floats2half2_rn(in[i], in[HH * WW + i]);
}

// Clip t so x(t)=bx-sn*t, y(t)=by+c*t stay inside (-1.01, 512.01); outside
// that, the bilinear support misses the image entirely (border gives 0).
__device__ __forceinline__ void clip_ray(float bx, float by, float sn, float c,
                                         int& k0, int& k1) {
    float tlo = -362.0f, thi = 362.0f;
    const float lo = -1.01f;
    const float hi = 512.01f;
    if (sn > 1e-7f) {
        float inv = __frcp_rn(sn);
        tlo = fmaxf(tlo, (bx - hi) * inv);
        thi = fminf(thi, (bx - lo) * inv);
    } else if (bx <= lo || bx >= hi) {
        thi = tlo - 1.0f;
    }
    if (c > 1e-7f) {
        float inv = __frcp_rn(c);
        tlo = fmaxf(tlo, (lo - by) * inv);
        thi = fminf(thi, (hi - by) * inv);
    } else if (c < -1e-7f) {
        float inv = __frcp_rn(c);
        tlo = fmaxf(tlo, (hi - by) * inv);
        thi = fminf(thi, (lo - by) * inv);
    } else if (by <= lo || by >= hi) {
        thi = tlo - 1.0f;
    }
    k0 = max(0, (int)ceilf(tlo + 362.0f));
    k1 = min(NT - 1, (int)floorf(thi + 362.0f));
}

__device__ __forceinline__ void ray_setup(int v, int s, float& sn, float& c,
                                          float& bxu, float& byu, int& k0, int& k1) {
    float theta = (float)v * (float)(M_PI / (double)NVIEW);
    sincosf(theta, &sn, &c);
    float sf = (float)s - 367.5f;
    float bx = fmaf(sf, c, 255.5f);
    float by = fmaf(sf, sn, 255.5f);
    clip_ray(bx, by, sn, c, k0, k1);
    bxu = bx + 0.5f;   // texel-center convention
    byu = by + 0.5f;
}

// Kernel A (tex): views |cos| >= sin. Warp tile 8 det x 4 t-offsets.
__global__ void __launch_bounds__(256) radonTexA(cudaTextureObject_t tex,
                                                 float* __restrict__ out) {
    int lane = threadIdx.x & 31;
    int warp = threadIdx.x >> 5;
    int si = lane & 7;
    int ti = lane >> 3;
    int s = blockIdx.x * 64 + warp * 8 + si;
    int vy = blockIdx.y;
    int v = (vy < 193) ? vy : (vy + 383);
    if (s >= NDCT) return;  // warp-uniform

    float sn, c, bxu, byu;
    int k0, k1;
    ray_setup(v, s, sn, c, bxu, byu, k0, k1);

    float accx = 0.0f, accy = 0.0f;
    float tf = (float)(k0 + ti) - 362.0f;
    #pragma unroll 4
    for (int k = k0 + ti; k <= k1; k += 4) {
        float u = fmaf(tf, -sn, bxu);
        float w = fmaf(tf, c, byu);
        float2 val = tex2D<float2>(tex, u, w);
        accx += val.x;
        accy += val.y;
        tf += 4.0f;
    }
    accx += __shfl_xor_sync(0xFFFFFFFFu, accx, 8);
    accy += __shfl_xor_sync(0xFFFFFFFFu, accy, 8);
    accx += __shfl_xor_sync(0xFFFFFFFFu, accx, 16);
    accy += __shfl_xor_sync(0xFFFFFFFFu, accy, 16);
    if (lane < 8) {
        out[v * NDCT + s] = accx;
        out[NVIEW * NDCT + v * NDCT + s] = accy;
    }
}

// Kernel B (tex): views sin > |cos|. Warp tile 4 det x 8 t-strides.
__global__ void __launch_bounds__(256) radonTexB(cudaTextureObject_t tex,
                                                 float* __restrict__ out) {
    int lane = threadIdx.x & 31;
    int warp = threadIdx.x >> 5;
    int si = lane & 3;
    int ti = lane >> 2;
    int s = blockIdx.x * 32 + warp * 4 + si;
    int v = 193 + blockIdx.y;

    float sn, c, bxu, byu;
    int k0, k1;
    ray_setup(v, s, sn, c, bxu, byu, k0, k1);

    float accx = 0.0f, accy = 0.0f;
    float tf = (float)(k0 + ti) - 362.0f;
    #pragma unroll 4
    for (int k = k0 + ti; k <= k1; k += 8) {
        float u = fmaf(tf, -sn, bxu);
        float w = fmaf(tf, c, byu);
        float2 val = tex2D<float2>(tex, u, w);
        accx += val.x;
        accy += val.y;
        tf += 8.0f;
    }
    accx += __shfl_xor_sync(0xFFFFFFFFu, accx, 4);
    accy += __shfl_xor_sync(0xFFFFFFFFu, accy, 4);
    accx += __shfl_xor_sync(0xFFFFFFFFu, accx, 8);
    accy += __shfl_xor_sync(0xFFFFFFFFu, accy, 8);
    accx += __shfl_xor_sync(0xFFFFFFFFu, accx, 16);
    accy += __shfl_xor_sync(0xFFFFFFFFu, accy, 16);
    if (lane < 4) {
        out[v * NDCT + s] = accx;
        out[NVIEW * NDCT + v * NDCT + s] = accy;
    }
}

// Fallback (no texture): manual 4-tap bilinear on g_himg. Thread per (v,s).
__global__ void __launch_bounds__(256) radonFallback(float* __restrict__ out) {
    int s = blockIdx.x * 256 + threadIdx.x;
    if (s >= NDCT) return;
    int v = blockIdx.y;

    float sn, c, bxu, byu;
    int k0, k1;
    ray_setup(v, s, sn, c, bxu, byu, k0, k1);
    float bx = bxu - 0.5f;
    float by = byu - 0.5f;

    float accx = 0.0f, accy = 0.0f;
    for (int k = k0; k <= k1; ++k) {
        float t = (float)k - 362.0f;
        float x = fmaf(t, -sn, bx);
        float y = fmaf(t, c, by);
        float fx = floorf(x), fy = floorf(y);
        int ix = (int)fx, iy = (int)fy;
        float wx = x - fx, wy = y - fy;
        float w00 = (1.0f - wx) * (1.0f - wy);
        float w01 = wx * (1.0f - wy);
        float w10 = (1.0f - wx) * wy;
        float w11 = wx * wy;
        float2 v00 = {0, 0}, v01 = {0, 0}, v10 = {0, 0}, v11 = {0, 0};
        bool x0ok = (unsigned)ix < WW, x1ok = (unsigned)(ix + 1) < WW;
        bool y0ok = (unsigned)iy < HH, y1ok = (unsigned)(iy + 1) < HH;
        if (x0ok && y0ok) v00 = __half22float2(g_himg[iy * WW + ix]);
        if (x1ok && y0ok) v01 = __half22float2(g_himg[iy * WW + ix + 1]);
        if (x0ok && y1ok) v10 = __half22float2(g_himg[(iy + 1) * WW + ix]);
        if (x1ok && y1ok) v11 = __half22float2(g_himg[(iy + 1) * WW + ix + 1]);
        accx += w00 * v00.x + w01 * v01.x + w10 * v10.x + w11 * v11.x;
        accy += w00 * v00.y + w01 * v01.y + w10 * v10.y + w11 * v11.y;
    }
    out[v * NDCT + s] = accx;
    out[NVIEW * NDCT + v * NDCT + s] = accy;
}

// Texture-object state: created ONCE on the first (uncaptured) call.
// 0 = untried, 1 = failed (use fallback), else = valid handle.
// Capture calls execute no runtime API — only kernel launches.
static cudaTextureObject_t s_tex = 0;

static void init_tex_once() {
    if (s_tex != 0) return;
    void* sym = nullptr;
    cudaError_t e = cudaGetSymbolAddress(&sym, g_himg);
    if (e == cudaSuccess) {
        cudaResourceDesc rd;
        memset(&rd, 0, sizeof(rd));
        rd.resType = cudaResourceTypePitch2D;
        rd.res.pitch2D.devPtr = sym;
        rd.res.pitch2D.desc = cudaCreateChannelDesc(16, 16, 0, 0, cudaChannelFormatKindFloat);
        rd.res.pitch2D.width = WW;
        rd.res.pitch2D.height = HH;
        rd.res.pitch2D.pitchInBytes = WW * sizeof(__half2);  // 2048B
        cudaTextureDesc td;
        memset(&td, 0, sizeof(td));
        td.addressMode[0] = cudaAddressModeBorder;
        td.addressMode[1] = cudaAddressModeBorder;
        td.filterMode = cudaFilterModeLinear;
        td.readMode = cudaReadModeElementType;
        td.normalizedCoords = 0;
        cudaTextureObject_t t = 0;
        e = cudaCreateTextureObject(&t, &rd, &td, nullptr);
        if (e == cudaSuccess && t != 0 && t != 1) {
            s_tex = t;   // stays valid for all graph replays
            return;
        }
    }
    cudaGetLastError();  // clear sticky error; fall back permanently
    s_tex = 1;
}

extern "C" void kernel_launch(void* const* d_in, const int* in_sizes, int n_in,
                              void* d_out, int out_size) {
    const float* in = (const float*)d_in[0];
    float* out = (float*)d_out;

    init_tex_once();  // no-op (no API calls) on every call after the first

    build_htex<<<(HH * WW + 255) / 256, 256>>>(in);

    if (s_tex != 1) {
        dim3 gridA((NDCT + 63) / 64, 385);
        radonTexA<<<gridA, 256>>>(s_tex, out);
        dim3 gridB(NDCT / 32, 383);
        radonTexB<<<gridB, 256>>>(s_tex, out);
    } else {
        dim3 gridF((NDCT + 255) / 256, NVIEW);
        radonFallback<<<gridF, 256>>>(out);
    }
}

// round 11
// speedup vs baseline: 4.0353x; 4.0353x over previous
#include <cuda_runtime.h>
#include <cuda_fp16.h>
#include <math.h>
#include <string.h>

#define HH 512
#define WW 512
#define NVIEW 768
#define NDCT 736
#define NT 725

// ---------- texture path data ----------
__device__ __align__(512) __half2 g_himg[HH * WW];

__global__ void build_htex(const float* __restrict__ in) {
    int i = blockIdx.x * blockDim.x + threadIdx.x;
    if (i < HH * WW)
        g_himg[i] = __floats2half2_rn(in[i], in[HH * WW + i]);
}

// ---------- fallback (R5) data: fp16 pair table ----------
#define PW 513
#define PH 514
struct __align__(8) HPair { __half2 lo, hi; };
__device__ HPair g_ph[PH * PW];

__global__ void build_pair(const float* __restrict__ in) {
    int i = blockIdx.x * blockDim.x + threadIdx.x;
    if (i >= PH * PW) return;
    int py = i / PW;
    int px = i - py * PW;
    int y = py - 1;
    int x0 = px - 1;
    float l0 = 0.0f, l1 = 0.0f, h0 = 0.0f, h1 = 0.0f;
    if (y >= 0 && y < HH) {
        if (x0 >= 0) {
            l0 = in[y * WW + x0];
            l1 = in[HH * WW + y * WW + x0];
        }
        if (px < WW) {
            h0 = in[y * WW + px];
            h1 = in[HH * WW + y * WW + px];
        }
    }
    HPair p;
    p.lo = __floats2half2_rn(l0, l1);
    p.hi = __floats2half2_rn(h0, h1);
    g_ph[i] = p;
}

// Clip t so the ray stays where the bilinear support may touch the image.
__device__ __forceinline__ void clip_ray(float bx, float by, float sn, float c,
                                         int& k0, int& k1) {
    float tlo = -362.0f, thi = 362.0f;
    const float lo = -0.999f;
    const float hi = 511.999f;
    if (sn > 1e-7f) {
        float inv = __frcp_rn(sn);
        tlo = fmaxf(tlo, (bx - hi) * inv);
        thi = fminf(thi, (bx - lo) * inv);
    } else if (bx <= lo || bx >= hi) {
        thi = tlo - 1.0f;
    }
    if (c > 1e-7f) {
        float inv = __frcp_rn(c);
        tlo = fmaxf(tlo, (lo - by) * inv);
        thi = fminf(thi, (hi - by) * inv);
    } else if (c < -1e-7f) {
        float inv = __frcp_rn(c);
        tlo = fmaxf(tlo, (hi - by) * inv);
        thi = fminf(thi, (lo - by) * inv);
    } else if (by <= lo || by >= hi) {
        thi = tlo - 1.0f;
    }
    k0 = max(0, (int)ceilf(tlo + 362.0f));
    k1 = min(NT - 1, (int)floorf(thi + 362.0f));
}

__device__ __forceinline__ void ray_setup(int v, int s, float& sn, float& c,
                                          float& bx, float& by, int& k0, int& k1) {
    float theta = (float)v * (float)(M_PI / (double)NVIEW);
    sincosf(theta, &sn, &c);
    float sf = (float)s - 367.5f;
    bx = fmaf(sf, c, 255.5f);
    by = fmaf(sf, sn, 255.5f);
    clip_ray(bx, by, sn, c, k0, k1);
}

// ================= TEXTURE KERNELS =================

// Kernel A (tex): views |cos| >= sin. Warp tile 8 det x 4 t-offsets.
__global__ void __launch_bounds__(256) radonTexA(cudaTextureObject_t tex,
                                                 float* __restrict__ out) {
    int lane = threadIdx.x & 31;
    int warp = threadIdx.x >> 5;
    int si = lane & 7;
    int ti = lane >> 3;
    int s = blockIdx.x * 64 + warp * 8 + si;
    int vy = blockIdx.y;
    int v = (vy < 193) ? vy : (vy + 383);
    if (s >= NDCT) return;  // warp-uniform

    float sn, c, bx, by;
    int k0, k1;
    ray_setup(v, s, sn, c, bx, by, k0, k1);
    float bxu = bx + 0.5f;
    float byu = by + 0.5f;

    float accx = 0.0f, accy = 0.0f;
    float tf = (float)(k0 + ti) - 362.0f;
    #pragma unroll 4
    for (int k = k0 + ti; k <= k1; k += 4) {
        float u = fmaf(tf, -sn, bxu);
        float w = fmaf(tf, c, byu);
        float2 val = tex2D<float2>(tex, u, w);
        accx += val.x;
        accy += val.y;
        tf += 4.0f;
    }
    accx += __shfl_xor_sync(0xFFFFFFFFu, accx, 8);
    accy += __shfl_xor_sync(0xFFFFFFFFu, accy, 8);
    accx += __shfl_xor_sync(0xFFFFFFFFu, accx, 16);
    accy += __shfl_xor_sync(0xFFFFFFFFu, accy, 16);
    if (lane < 8) {
        out[v * NDCT + s] = accx;
        out[NVIEW * NDCT + v * NDCT + s] = accy;
    }
}

// Kernel B (tex): views sin > |cos|. Warp tile 4 det x 8 t-strides.
__global__ void __launch_bounds__(256) radonTexB(cudaTextureObject_t tex,
                                                 float* __restrict__ out) {
    int lane = threadIdx.x & 31;
    int warp = threadIdx.x >> 5;
    int si = lane & 3;
    int ti = lane >> 2;
    int s = blockIdx.x * 32 + warp * 4 + si;
    int v = 193 + blockIdx.y;

    float sn, c, bx, by;
    int k0, k1;
    ray_setup(v, s, sn, c, bx, by, k0, k1);
    float bxu = bx + 0.5f;
    float byu = by + 0.5f;

    float accx = 0.0f, accy = 0.0f;
    float tf = (float)(k0 + ti) - 362.0f;
    #pragma unroll 4
    for (int k = k0 + ti; k <= k1; k += 8) {
        float u = fmaf(tf, -sn, bxu);
        float w = fmaf(tf, c, byu);
        float2 val = tex2D<float2>(tex, u, w);
        accx += val.x;
        accy += val.y;
        tf += 8.0f;
    }
    accx += __shfl_xor_sync(0xFFFFFFFFu, accx, 4);
    accy += __shfl_xor_sync(0xFFFFFFFFu, accy, 4);
    accx += __shfl_xor_sync(0xFFFFFFFFu, accx, 8);
    accy += __shfl_xor_sync(0xFFFFFFFFu, accy, 8);
    accx += __shfl_xor_sync(0xFFFFFFFFu, accx, 16);
    accy += __shfl_xor_sync(0xFFFFFFFFu, accy, 16);
    if (lane < 4) {
        out[v * NDCT + s] = accx;
        out[NVIEW * NDCT + v * NDCT + s] = accy;
    }
}

// ================= FALLBACK KERNELS (R5, 365us known-good) =================

#define MAGIC 8388608.0f  // 2^23

__device__ __forceinline__ void sample_h(float xp, float yp, __half2& pacc) {
    float sx = __fadd_rd(xp, MAGIC);
    float sy = __fadd_rd(yp, MAGIC);
    int ixp = __float_as_int(sx) & 0x7FFFFF;
    int iyp = __float_as_int(sy) & 0x7FFFFF;
    float wx = xp - (sx - MAGIC);
    float wy = yp - (sy - MAGIC);
    __half2 wxh = __float2half2_rn(wx);
    __half2 wyh = __float2half2_rn(wy);
    int base = iyp * PW + ixp;
    HPair r0 = g_ph[base];
    HPair r1 = g_ph[base + PW];
    __half2 a0 = __hfma2(wxh, __hsub2(r0.hi, r0.lo), r0.lo);
    __half2 a1 = __hfma2(wxh, __hsub2(r1.hi, r1.lo), r1.lo);
    __half2 val = __hfma2(wyh, __hsub2(a1, a0), a0);
    pacc = __hadd2(pacc, val);
}

template <int STRIDE>
__device__ __forceinline__ void integrate(int k0, int k1, int ti,
                                          float sn, float c, float bxp, float byp,
                                          float& accx, float& accy) {
    int k = k0 + ti;
    float tf = (float)k - 362.0f;
    while (k <= k1) {
        __half2 pacc = __float2half2_rn(0.0f);
        #pragma unroll
        for (int u = 0; u < 8; ++u) {
            if (k <= k1) {
                float xp = fmaf(tf, -sn, bxp);
                float yp = fmaf(tf, c, byp);
                sample_h(xp, yp, pacc);
            }
            k += STRIDE;
            tf += (float)STRIDE;
        }
        float2 f = __half22float2(pacc);
        accx += f.x;
        accy += f.y;
    }
}

__global__ void __launch_bounds__(256) radonFbA(float* __restrict__ out) {
    int lane = threadIdx.x & 31;
    int warp = threadIdx.x >> 5;
    int si = lane & 7;
    int ti = lane >> 3;
    int s = blockIdx.x * 64 + warp * 8 + si;
    int vy = blockIdx.y;
    int v = (vy < 193) ? vy : (vy + 383);
    if (s >= NDCT) return;

    float sn, c, bx, by;
    int k0, k1;
    ray_setup(v, s, sn, c, bx, by, k0, k1);

    float accx = 0.0f, accy = 0.0f;
    integrate<4>(k0, k1, ti, sn, c, bx + 1.0f, by + 1.0f, accx, accy);

    accx += __shfl_xor_sync(0xFFFFFFFFu, accx, 8);
    accy += __shfl_xor_sync(0xFFFFFFFFu, accy, 8);
    accx += __shfl_xor_sync(0xFFFFFFFFu, accx, 16);
    accy += __shfl_xor_sync(0xFFFFFFFFu, accy, 16);
    if (lane < 8) {
        out[v * NDCT + s] = accx;
        out[NVIEW * NDCT + v * NDCT + s] = accy;
    }
}

__global__ void __launch_bounds__(256) radonFbB(float* __restrict__ out) {
    int lane = threadIdx.x & 31;
    int warp = threadIdx.x >> 5;
    int si = lane & 3;
    int ti = lane >> 2;
    int s = blockIdx.x * 32 + warp * 4 + si;
    int v = 193 + blockIdx.y;

    float sn, c, bx, by;
    int k0, k1;
    ray_setup(v, s, sn, c, bx, by, k0, k1);

    float accx = 0.0f, accy = 0.0f;
    integrate<8>(k0, k1, ti, sn, c, bx + 1.0f, by + 1.0f, accx, accy);

    accx += __shfl_xor_sync(0xFFFFFFFFu, accx, 4);
    accy += __shfl_xor_sync(0xFFFFFFFFu, accy, 4);
    accx += __shfl_xor_sync(0xFFFFFFFFu, accx, 8);
    accy += __shfl_xor_sync(0xFFFFFFFFu, accy, 8);
    accx += __shfl_xor_sync(0xFFFFFFFFu, accx, 16);
    accy += __shfl_xor_sync(0xFFFFFFFFu, accy, 16);
    if (lane < 4) {
        out[v * NDCT + s] = accx;
        out[NVIEW * NDCT + v * NDCT + s] = accy;
    }
}

// ---------- one-time texture creation (first, uncaptured call only) ----------
static int s_state = 0;                 // 0 untried, 1 tex ok, 2 fallback
static cudaTextureObject_t s_tex = 0;   // handle may legitimately be any value

static void init_tex_once() {
    if (s_state != 0) return;
    void* sym = nullptr;
    cudaError_t e = cudaGetSymbolAddress(&sym, g_himg);
    if (e == cudaSuccess) {
        cudaResourceDesc rd;
        memset(&rd, 0, sizeof(rd));
        rd.resType = cudaResourceTypePitch2D;
        rd.res.pitch2D.devPtr = sym;
        rd.res.pitch2D.desc = cudaCreateChannelDesc(16, 16, 0, 0, cudaChannelFormatKindFloat);
        rd.res.pitch2D.width = WW;
        rd.res.pitch2D.height = HH;
        rd.res.pitch2D.pitchInBytes = WW * sizeof(__half2);  // 2048B
        cudaTextureDesc td;
        memset(&td, 0, sizeof(td));
        td.addressMode[0] = cudaAddressModeBorder;
        td.addressMode[1] = cudaAddressModeBorder;
        td.filterMode = cudaFilterModeLinear;
        td.readMode = cudaReadModeElementType;
        td.normalizedCoords = 0;
        e = cudaCreateTextureObject(&s_tex, &rd, &td, nullptr);
        if (e == cudaSuccess) {
            s_state = 1;   // handle stays valid for all graph replays
            return;
        }
    }
    cudaGetLastError();   // clear sticky error
    s_state = 2;
}

extern "C" void kernel_launch(void* const* d_in, const int* in_sizes, int n_in,
                              void* d_out, int out_size) {
    const float* in = (const float*)d_in[0];
    float* out = (float*)d_out;

    init_tex_once();   // no API calls after the first invocation

    if (s_state == 1) {
        build_htex<<<(HH * WW + 255) / 256, 256>>>(in);
        dim3 gridA((NDCT + 63) / 64, 385);
        radonTexA<<<gridA, 256>>>(s_tex, out);
        dim3 gridB(NDCT / 32, 383);
        radonTexB<<<gridB, 256>>>(s_tex, out);
    } else {
        build_pair<<<(PH * PW + 255) / 256, 256>>>(in);
        dim3 gridA((NDCT + 63) / 64, 385);
        radonFbA<<<gridA, 256>>>(out);
        dim3 gridB(NDCT / 32, 383);
        radonFbB<<<gridB, 256>>>(out);
    }
}

// round 12
// speedup vs baseline: 4.0548x; 1.0048x over previous
#include <cuda_runtime.h>
#include <cuda_fp16.h>
#include <math.h>
#include <string.h>

#define HH 512
#define WW 512
#define NVIEW 768
#define NDCT 736
#define NT 725

#define PW 513
#define PH 514

// texture image: half2 (ch0,ch1) per texel
__device__ __align__(512) __half2 g_himg[HH * WW];
// manual-path pair table: entry px covers image columns px-1,px; zero border
struct __align__(8) HPair { __half2 lo, hi; };
__device__ HPair g_ph[PH * PW];

__global__ void build_tables(const float* __restrict__ in) {
    int i = blockIdx.x * blockDim.x + threadIdx.x;
    if (i < HH * WW)
        g_himg[i] = __floats2half2_rn(in[i], in[HH * WW + i]);
    if (i < PH * PW) {
        int py = i / PW;
        int px = i - py * PW;
        int y = py - 1;
        int x0 = px - 1;
        float l0 = 0.0f, l1 = 0.0f, h0 = 0.0f, h1 = 0.0f;
        if (y >= 0 && y < HH) {
            if (x0 >= 0) {
                l0 = in[y * WW + x0];
                l1 = in[HH * WW + y * WW + x0];
            }
            if (px < WW) {
                h0 = in[y * WW + px];
                h1 = in[HH * WW + y * WW + px];
            }
        }
        HPair p;
        p.lo = __floats2half2_rn(l0, l1);
        p.hi = __floats2half2_rn(h0, h1);
        g_ph[i] = p;
    }
}

__device__ __forceinline__ void clip_ray(float bx, float by, float sn, float c,
                                         int& k0, int& k1) {
    float tlo = -362.0f, thi = 362.0f;
    const float lo = -0.999f;
    const float hi = 511.999f;
    if (sn > 1e-7f) {
        float inv = __frcp_rn(sn);
        tlo = fmaxf(tlo, (bx - hi) * inv);
        thi = fminf(thi, (bx - lo) * inv);
    } else if (bx <= lo || bx >= hi) {
        thi = tlo - 1.0f;
    }
    if (c > 1e-7f) {
        float inv = __frcp_rn(c);
        tlo = fmaxf(tlo, (lo - by) * inv);
        thi = fminf(thi, (hi - by) * inv);
    } else if (c < -1e-7f) {
        float inv = __frcp_rn(c);
        tlo = fmaxf(tlo, (hi - by) * inv);
        thi = fminf(thi, (lo - by) * inv);
    } else if (by <= lo || by >= hi) {
        thi = tlo - 1.0f;
    }
    k0 = max(0, (int)ceilf(tlo + 362.0f));
    k1 = min(NT - 1, (int)floorf(thi + 362.0f));
}

__device__ __forceinline__ void ray_setup(int v, int s, float& sn, float& c,
                                          float& bx, float& by, int& k0, int& k1) {
    float theta = (float)v * (float)(M_PI / (double)NVIEW);
    sincosf(theta, &sn, &c);
    float sf = (float)s - 367.5f;
    bx = fmaf(sf, c, 255.5f);
    by = fmaf(sf, sn, 255.5f);
    clip_ray(bx, by, sn, c, k0, k1);
}

#define MAGIC 8388608.0f  // 2^23

__device__ __forceinline__ void sample_h(float xp, float yp, __half2& pacc) {
    float sx = __fadd_rd(xp, MAGIC);
    float sy = __fadd_rd(yp, MAGIC);
    int ixp = __float_as_int(sx) & 0x7FFFFF;
    int iyp = __float_as_int(sy) & 0x7FFFFF;
    float wx = xp - (sx - MAGIC);
    float wy = yp - (sy - MAGIC);
    __half2 wxh = __float2half2_rn(wx);
    __half2 wyh = __float2half2_rn(wy);
    int base = iyp * PW + ixp;
    HPair r0 = g_ph[base];
    HPair r1 = g_ph[base + PW];
    __half2 a0 = __hfma2(wxh, __hsub2(r0.hi, r0.lo), r0.lo);
    __half2 a1 = __hfma2(wxh, __hsub2(r1.hi, r1.lo), r1.lo);
    __half2 val = __hfma2(wyh, __hsub2(a1, a0), a0);
    pacc = __hadd2(pacc, val);
}

template <int STRIDE>
__device__ __forceinline__ void integrate(int k0, int k1, int ti,
                                          float sn, float c, float bxp, float byp,
                                          float& accx, float& accy) {
    int k = k0 + ti;
    float tf = (float)k - 362.0f;
    while (k <= k1) {
        __half2 pacc = __float2half2_rn(0.0f);
        #pragma unroll
        for (int u = 0; u < 8; ++u) {
            if (k <= k1) {
                float xp = fmaf(tf, -sn, bxp);
                float yp = fmaf(tf, c, byp);
                sample_h(xp, yp, pacc);
            }
            k += STRIDE;
            tf += (float)STRIDE;
        }
        float2 f = __half22float2(pacc);
        accx += f.x;
        accy += f.y;
    }
}

template <int STRIDE>
__device__ __forceinline__ void integrate_tex(cudaTextureObject_t tex,
                                              int k0, int k1, int ti,
                                              float sn, float c, float bxu, float byu,
                                              float& accx, float& accy) {
    float tf = (float)(k0 + ti) - 362.0f;
    #pragma unroll 4
    for (int k = k0 + ti; k <= k1; k += STRIDE) {
        float u = fmaf(tf, -sn, bxu);
        float w = fmaf(tf, c, byu);
        float2 val = tex2D<float2>(tex, u, w);
        accx += val.x;
        accy += val.y;
        tf += (float)STRIDE;
    }
}

__device__ __forceinline__ void reduce_store(float accx, float accy, int lane,
                                             int dpw, int v, int s,
                                             float* __restrict__ out) {
    #pragma unroll
    for (int off = 4; off < 32; off <<= 1) {
        if (off >= dpw) {
            accx += __shfl_xor_sync(0xFFFFFFFFu, accx, off);
            accy += __shfl_xor_sync(0xFFFFFFFFu, accy, off);
        }
    }
    if (lane < dpw) {
        out[v * NDCT + s] = accx;
        out[NVIEW * NDCT + v * NDCT + s] = accy;
    }
}

// View partition (interleaved mod 16): manual gets residues 0..6 (7/16),
// TEX gets residues 7..15 (9/16). Closed-form i-th member decode.
// Slot layout in blockIdx.y: [0,216) TEXA | [216,431) TEXB | [431,600) MANA | [600,768) MANB.
__global__ void __launch_bounds__(256) radonHybrid(cudaTextureObject_t tex,
                                                   float* __restrict__ out) {
    int lane = threadIdx.x & 31;
    int warp = threadIdx.x >> 5;
    int by = blockIdx.y;

    if (by < 216) {                    // TEX, A-class (9/16 of 385 views)
        if (blockIdx.x >= 12) return;
        int i = by;
        int vy = (i / 9) * 16 + 7 + (i % 9);
        int v = (vy < 193) ? vy : (vy + 383);
        int si = lane & 7, ti = lane >> 3;
        int s = blockIdx.x * 64 + warp * 8 + si;
        if (s >= NDCT) return;
        float sn, c, bx, byv; int k0, k1;
        ray_setup(v, s, sn, c, bx, byv, k0, k1);
        float accx = 0.0f, accy = 0.0f;
        integrate_tex<4>(tex, k0, k1, ti, sn, c, bx + 0.5f, byv + 0.5f, accx, accy);
        reduce_store(accx, accy, lane, 8, v, s, out);
    } else if (by < 431) {             // TEX, B-class
        int i = by - 216;
        int vv = (i / 9) * 16 + 7 + (i % 9);
        int v = 193 + vv;
        int si = lane & 3, ti = lane >> 2;
        int s = blockIdx.x * 32 + warp * 4 + si;
        float sn, c, bx, byv; int k0, k1;
        ray_setup(v, s, sn, c, bx, byv, k0, k1);
        float accx = 0.0f, accy = 0.0f;
        integrate_tex<8>(tex, k0, k1, ti, sn, c, bx + 0.5f, byv + 0.5f, accx, accy);
        reduce_store(accx, accy, lane, 4, v, s, out);
    } else if (by < 600) {             // MANUAL, A-class (7/16)
        if (blockIdx.x >= 12) return;
        int i = by - 431;
        int vy = (i / 7) * 16 + (i % 7);
        int v = (vy < 193) ? vy : (vy + 383);
        int si = lane & 7, ti = lane >> 3;
        int s = blockIdx.x * 64 + warp * 8 + si;
        if (s >= NDCT) return;
        float sn, c, bx, byv; int k0, k1;
        ray_setup(v, s, sn, c, bx, byv, k0, k1);
        float accx = 0.0f, accy = 0.0f;
        integrate<4>(k0, k1, ti, sn, c, bx + 1.0f, byv + 1.0f, accx, accy);
        reduce_store(accx, accy, lane, 8, v, s, out);
    } else {                           // MANUAL, B-class
        int i = by - 600;
        int vv = (i / 7) * 16 + (i % 7);
        int v = 193 + vv;
        int si = lane & 3, ti = lane >> 2;
        int s = blockIdx.x * 32 + warp * 4 + si;
        float sn, c, bx, byv; int k0, k1;
        ray_setup(v, s, sn, c, bx, byv, k0, k1);
        float accx = 0.0f, accy = 0.0f;
        integrate<8>(k0, k1, ti, sn, c, bx + 1.0f, byv + 1.0f, accx, accy);
        reduce_store(accx, accy, lane, 4, v, s, out);
    }
}

// ---- pure-manual fallback (R5) if texture creation is unavailable ----
__global__ void __launch_bounds__(256) radonFbA(float* __restrict__ out) {
    int lane = threadIdx.x & 31, warp = threadIdx.x >> 5;
    int si = lane & 7, ti = lane >> 3;
    int s = blockIdx.x * 64 + warp * 8 + si;
    int vy = blockIdx.y;
    int v = (vy < 193) ? vy : (vy + 383);
    if (s >= NDCT) return;
    float sn, c, bx, byv; int k0, k1;
    ray_setup(v, s, sn, c, bx, byv, k0, k1);
    float accx = 0.0f, accy = 0.0f;
    integrate<4>(k0, k1, ti, sn, c, bx + 1.0f, byv + 1.0f, accx, accy);
    reduce_store(accx, accy, lane, 8, v, s, out);
}
__global__ void __launch_bounds__(256) radonFbB(float* __restrict__ out) {
    int lane = threadIdx.x & 31, warp = threadIdx.x >> 5;
    int si = lane & 3, ti = lane >> 2;
    int s = blockIdx.x * 32 + warp * 4 + si;
    int v = 193 + blockIdx.y;
    float sn, c, bx, byv; int k0, k1;
    ray_setup(v, s, sn, c, bx, byv, k0, k1);
    float accx = 0.0f, accy = 0.0f;
    integrate<8>(k0, k1, ti, sn, c, bx + 1.0f, byv + 1.0f, accx, accy);
    reduce_store(accx, accy, lane, 4, v, s, out);
}

// ---- one-time texture creation (first, uncaptured call only) ----
static int s_state = 0;                 // 0 untried, 1 tex ok, 2 fallback
static cudaTextureObject_t s_tex = 0;

static void init_tex_once() {
    if (s_state != 0) return;
    void* sym = nullptr;
    cudaError_t e = cudaGetSymbolAddress(&sym, g_himg);
    if (e == cudaSuccess) {
        cudaResourceDesc rd;
        memset(&rd, 0, sizeof(rd));
        rd.resType = cudaResourceTypePitch2D;
        rd.res.pitch2D.devPtr = sym;
        rd.res.pitch2D.desc = cudaCreateChannelDesc(16, 16, 0, 0, cudaChannelFormatKindFloat);
        rd.res.pitch2D.width = WW;
        rd.res.pitch2D.height = HH;
        rd.res.pitch2D.pitchInBytes = WW * sizeof(__half2);
        cudaTextureDesc td;
        memset(&td, 0, sizeof(td));
        td.addressMode[0] = cudaAddressModeBorder;
        td.addressMode[1] = cudaAddressModeBorder;
        td.filterMode = cudaFilterModeLinear;
        td.readMode = cudaReadModeElementType;
        td.normalizedCoords = 0;
        e = cudaCreateTextureObject(&s_tex, &rd, &td, nullptr);
        if (e == cudaSuccess) { s_state = 1; return; }
    }
    cudaGetLastError();
    s_state = 2;
}

extern "C" void kernel_launch(void* const* d_in, const int* in_sizes, int n_in,
                              void* d_out, int out_size) {
    const float* in = (const float*)d_in[0];
    float* out = (float*)d_out;

    init_tex_once();

    build_tables<<<(PH * PW + 255) / 256, 256>>>(in);

    if (s_state == 1) {
        dim3 grid(23, 768);   // x: det tiles (A uses 12, B uses 23); y: path slots
        radonHybrid<<<grid, 256>>>(s_tex, out);
    } else {
        dim3 gridA((NDCT + 63) / 64, 385);
        radonFbA<<<gridA, 256>>>(out);
        dim3 gridB(NDCT / 32, 383);
        radonFbB<<<gridB, 256>>>(out);
    }
}

// round 13
// speedup vs baseline: 4.4856x; 1.1062x over previous
#include <cuda_runtime.h>
#include <cuda_fp16.h>
#include <math.h>
#include <string.h>

#define HH 512
#define WW 512
#define NVIEW 768
#define NDCT 736
#define NT 725

#define PW 513
#define PH 514

// texture image: half2 (ch0,ch1) per texel
__device__ __align__(512) __half2 g_himg[HH * WW];
// fallback pair table (manual path): entry px covers image cols px-1,px; zero border
struct __align__(8) HPair { __half2 lo, hi; };
__device__ HPair g_ph[PH * PW];

__global__ void build_tables(const float* __restrict__ in) {
    int i = blockIdx.x * blockDim.x + threadIdx.x;
    if (i < HH * WW)
        g_himg[i] = __floats2half2_rn(in[i], in[HH * WW + i]);
    if (i < PH * PW) {
        int py = i / PW;
        int px = i - py * PW;
        int y = py - 1;
        int x0 = px - 1;
        float l0 = 0.0f, l1 = 0.0f, h0 = 0.0f, h1 = 0.0f;
        if (y >= 0 && y < HH) {
            if (x0 >= 0) {
                l0 = in[y * WW + x0];
                l1 = in[HH * WW + y * WW + x0];
            }
            if (px < WW) {
                h0 = in[y * WW + px];
                h1 = in[HH * WW + y * WW + px];
            }
        }
        HPair p;
        p.lo = __floats2half2_rn(l0, l1);
        p.hi = __floats2half2_rn(h0, h1);
        g_ph[i] = p;
    }
}

__device__ __forceinline__ void clip_ray(float bx, float by, float sn, float c,
                                         int& k0, int& k1) {
    float tlo = -362.0f, thi = 362.0f;
    const float lo = -0.999f;
    const float hi = 511.999f;
    if (sn > 1e-7f) {
        float inv = __frcp_rn(sn);
        tlo = fmaxf(tlo, (bx - hi) * inv);
        thi = fminf(thi, (bx - lo) * inv);
    } else if (bx <= lo || bx >= hi) {
        thi = tlo - 1.0f;
    }
    if (c > 1e-7f) {
        float inv = __frcp_rn(c);
        tlo = fmaxf(tlo, (lo - by) * inv);
        thi = fminf(thi, (hi - by) * inv);
    } else if (c < -1e-7f) {
        float inv = __frcp_rn(c);
        tlo = fmaxf(tlo, (hi - by) * inv);
        thi = fminf(thi, (lo - by) * inv);
    } else if (by <= lo || by >= hi) {
        thi = tlo - 1.0f;
    }
    k0 = max(0, (int)ceilf(tlo + 362.0f));
    k1 = min(NT - 1, (int)floorf(thi + 362.0f));
}

__device__ __forceinline__ void ray_setup(int v, int s, float& sn, float& c,
                                          float& bx, float& by, int& k0, int& k1) {
    float theta = (float)v * (float)(M_PI / (double)NVIEW);
    sincosf(theta, &sn, &c);
    float sf = (float)s - 367.5f;
    bx = fmaf(sf, c, 255.5f);
    by = fmaf(sf, sn, 255.5f);
    clip_ray(bx, by, sn, c, k0, k1);
}

// Deep-ILP tex integration: 8 outstanding TEX per thread, dual accumulator pairs.
template <int STRIDE>
__device__ __forceinline__ void integrate_tex(cudaTextureObject_t tex,
                                              int k0, int k1, int ti,
                                              float sn, float c, float bxu, float byu,
                                              float& accx, float& accy) {
    float a0x = 0.0f, a0y = 0.0f, a1x = 0.0f, a1y = 0.0f;
    int k = k0 + ti;
    float tf = (float)k - 362.0f;
    while (k <= k1) {
        #pragma unroll
        for (int u = 0; u < 8; ++u) {
            if (k <= k1) {
                float tfu = tf + (float)(u * STRIDE);
                float uu = fmaf(tfu, -sn, bxu);
                float wv = fmaf(tfu, c, byu);
                float2 val = tex2D<float2>(tex, uu, wv);
                if (u & 1) { a1x += val.x; a1y += val.y; }
                else       { a0x += val.x; a0y += val.y; }
            }
            k += STRIDE;
        }
        tf += (float)(8 * STRIDE);
    }
    accx = a0x + a1x;
    accy = a0y + a1y;
}

__device__ __forceinline__ void reduce_store(float accx, float accy, int lane,
                                             int dpw, int v, int s,
                                             float* __restrict__ out) {
    #pragma unroll
    for (int off = 4; off < 32; off <<= 1) {
        if (off >= dpw) {
            accx += __shfl_xor_sync(0xFFFFFFFFu, accx, off);
            accy += __shfl_xor_sync(0xFFFFFFFFu, accy, off);
        }
    }
    if (lane < dpw) {
        out[v * NDCT + s] = accx;
        out[NVIEW * NDCT + v * NDCT + s] = accy;
    }
}

// Kernel A (tex): views |cos| >= sin. Warp tile 8 det x 4 t-offsets.
__global__ void __launch_bounds__(256) radonTexA(cudaTextureObject_t tex,
                                                 float* __restrict__ out) {
    int lane = threadIdx.x & 31;
    int warp = threadIdx.x >> 5;
    int si = lane & 7;
    int ti = lane >> 3;
    int s = blockIdx.x * 64 + warp * 8 + si;
    int vy = blockIdx.y;
    int v = (vy < 193) ? vy : (vy + 383);
    if (s >= NDCT) return;  // warp-uniform

    float sn, c, bx, by;
    int k0, k1;
    ray_setup(v, s, sn, c, bx, by, k0, k1);

    float accx, accy;
    integrate_tex<4>(tex, k0, k1, ti, sn, c, bx + 0.5f, by + 0.5f, accx, accy);
    reduce_store(accx, accy, lane, 8, v, s, out);
}

// Kernel B (tex): views sin > |cos|. Warp tile 4 det x 8 t-strides.
__global__ void __launch_bounds__(256) radonTexB(cudaTextureObject_t tex,
                                                 float* __restrict__ out) {
    int lane = threadIdx.x & 31;
    int warp = threadIdx.x >> 5;
    int si = lane & 3;
    int ti = lane >> 2;
    int s = blockIdx.x * 32 + warp * 4 + si;
    int v = 193 + blockIdx.y;

    float sn, c, bx, by;
    int k0, k1;
    ray_setup(v, s, sn, c, bx, by, k0, k1);

    float accx, accy;
    integrate_tex<8>(tex, k0, k1, ti, sn, c, bx + 0.5f, by + 0.5f, accx, accy);
    reduce_store(accx, accy, lane, 4, v, s, out);
}

// ================= FALLBACK (R5 manual) =================
#define MAGIC 8388608.0f  // 2^23

__device__ __forceinline__ void sample_h(float xp, float yp, __half2& pacc) {
    float sx = __fadd_rd(xp, MAGIC);
    float sy = __fadd_rd(yp, MAGIC);
    int ixp = __float_as_int(sx) & 0x7FFFFF;
    int iyp = __float_as_int(sy) & 0x7FFFFF;
    float wx = xp - (sx - MAGIC);
    float wy = yp - (sy - MAGIC);
    __half2 wxh = __float2half2_rn(wx);
    __half2 wyh = __float2half2_rn(wy);
    int base = iyp * PW + ixp;
    HPair r0 = g_ph[base];
    HPair r1 = g_ph[base + PW];
    __half2 a0 = __hfma2(wxh, __hsub2(r0.hi, r0.lo), r0.lo);
    __half2 a1 = __hfma2(wxh, __hsub2(r1.hi, r1.lo), r1.lo);
    __half2 val = __hfma2(wyh, __hsub2(a1, a0), a0);
    pacc = __hadd2(pacc, val);
}

template <int STRIDE>
__device__ __forceinline__ void integrate(int k0, int k1, int ti,
                                          float sn, float c, float bxp, float byp,
                                          float& accx, float& accy) {
    int k = k0 + ti;
    float tf = (float)k - 362.0f;
    while (k <= k1) {
        __half2 pacc = __float2half2_rn(0.0f);
        #pragma unroll
        for (int u = 0; u < 8; ++u) {
            if (k <= k1) {
                float xp = fmaf(tf, -sn, bxp);
                float yp = fmaf(tf, c, byp);
                sample_h(xp, yp, pacc);
            }
            k += STRIDE;
            tf += (float)STRIDE;
        }
        float2 f = __half22float2(pacc);
        accx += f.x;
        accy += f.y;
    }
}

__global__ void __launch_bounds__(256) radonFbA(float* __restrict__ out) {
    int lane = threadIdx.x & 31, warp = threadIdx.x >> 5;
    int si = lane & 7, ti = lane >> 3;
    int s = blockIdx.x * 64 + warp * 8 + si;
    int vy = blockIdx.y;
    int v = (vy < 193) ? vy : (vy + 383);
    if (s >= NDCT) return;
    float sn, c, bx, byv; int k0, k1;
    ray_setup(v, s, sn, c, bx, byv, k0, k1);
    float accx = 0.0f, accy = 0.0f;
    integrate<4>(k0, k1, ti, sn, c, bx + 1.0f, byv + 1.0f, accx, accy);
    reduce_store(accx, accy, lane, 8, v, s, out);
}
__global__ void __launch_bounds__(256) radonFbB(float* __restrict__ out) {
    int lane = threadIdx.x & 31, warp = threadIdx.x >> 5;
    int si = lane & 3, ti = lane >> 2;
    int s = blockIdx.x * 32 + warp * 4 + si;
    int v = 193 + blockIdx.y;
    float sn, c, bx, byv; int k0, k1;
    ray_setup(v, s, sn, c, bx, byv, k0, k1);
    float accx = 0.0f, accy = 0.0f;
    integrate<8>(k0, k1, ti, sn, c, bx + 1.0f, byv + 1.0f, accx, accy);
    reduce_store(accx, accy, lane, 4, v, s, out);
}

// ---- one-time texture creation (first, uncaptured call only) ----
static int s_state = 0;                 // 0 untried, 1 tex ok, 2 fallback
static cudaTextureObject_t s_tex = 0;

static void init_tex_once() {
    if (s_state != 0) return;
    void* sym = nullptr;
    cudaError_t e = cudaGetSymbolAddress(&sym, g_himg);
    if (e == cudaSuccess) {
        cudaResourceDesc rd;
        memset(&rd, 0, sizeof(rd));
        rd.resType = cudaResourceTypePitch2D;
        rd.res.pitch2D.devPtr = sym;
        rd.res.pitch2D.desc = cudaCreateChannelDesc(16, 16, 0, 0, cudaChannelFormatKindFloat);
        rd.res.pitch2D.width = WW;
        rd.res.pitch2D.height = HH;
        rd.res.pitch2D.pitchInBytes = WW * sizeof(__half2);
        cudaTextureDesc td;
        memset(&td, 0, sizeof(td));
        td.addressMode[0] = cudaAddressModeBorder;
        td.addressMode[1] = cudaAddressModeBorder;
        td.filterMode = cudaFilterModeLinear;
        td.readMode = cudaReadModeElementType;
        td.normalizedCoords = 0;
        e = cudaCreateTextureObject(&s_tex, &rd, &td, nullptr);
        if (e == cudaSuccess) { s_state = 1; return; }
    }
    cudaGetLastError();
    s_state = 2;
}

extern "C" void kernel_launch(void* const* d_in, const int* in_sizes, int n_in,
                              void* d_out, int out_size) {
    const float* in = (const float*)d_in[0];
    float* out = (float*)d_out;

    init_tex_once();

    build_tables<<<(PH * PW + 255) / 256, 256>>>(in);

    if (s_state == 1) {
        dim3 gridA((NDCT + 63) / 64, 385);
        radonTexA<<<gridA, 256>>>(s_tex, out);
        dim3 gridB(NDCT / 32, 383);
        radonTexB<<<gridB, 256>>>(s_tex, out);
    } else {
        dim3 gridA((NDCT + 63) / 64, 385);
        radonFbA<<<gridA, 256>>>(out);
        dim3 gridB(NDCT / 32, 383);
        radonFbB<<<gridB, 256>>>(out);
    }
}

// round 14
// speedup vs baseline: 6.4834x; 1.4454x over previous
#include <cuda_runtime.h>
#include <cuda_fp16.h>
#include <math.h>
#include <string.h>

#define HH 512
#define WW 512
#define NVIEW 768
#define NDCT 736
#define NT 725

#define PW 513
#define PH 514

// texture image: half2 (ch0,ch1) per texel
__device__ __align__(512) __half2 g_himg[HH * WW];
// fallback pair table (manual path)
struct __align__(8) HPair { __half2 lo, hi; };
__device__ HPair g_ph[PH * PW];

__global__ void build_tables(const float* __restrict__ in) {
    int i = blockIdx.x * blockDim.x + threadIdx.x;
    if (i < HH * WW)
        g_himg[i] = __floats2half2_rn(in[i], in[HH * WW + i]);
    if (i < PH * PW) {
        int py = i / PW;
        int px = i - py * PW;
        int y = py - 1;
        int x0 = px - 1;
        float l0 = 0.0f, l1 = 0.0f, h0 = 0.0f, h1 = 0.0f;
        if (y >= 0 && y < HH) {
            if (x0 >= 0) {
                l0 = in[y * WW + x0];
                l1 = in[HH * WW + y * WW + x0];
            }
            if (px < WW) {
                h0 = in[y * WW + px];
                h1 = in[HH * WW + y * WW + px];
            }
        }
        HPair p;
        p.lo = __floats2half2_rn(l0, l1);
        p.hi = __floats2half2_rn(h0, h1);
        g_ph[i] = p;
    }
}

__device__ __forceinline__ void clip_ray(float bx, float by, float sn, float c,
                                         int& k0, int& k1) {
    float tlo = -362.0f, thi = 362.0f;
    const float lo = -0.999f;
    const float hi = 511.999f;
    if (sn > 1e-7f) {
        float inv = __frcp_rn(sn);
        tlo = fmaxf(tlo, (bx - hi) * inv);
        thi = fminf(thi, (bx - lo) * inv);
    } else if (bx <= lo || bx >= hi) {
        thi = tlo - 1.0f;
    }
    if (c > 1e-7f) {
        float inv = __frcp_rn(c);
        tlo = fmaxf(tlo, (lo - by) * inv);
        thi = fminf(thi, (hi - by) * inv);
    } else if (c < -1e-7f) {
        float inv = __frcp_rn(c);
        tlo = fmaxf(tlo, (hi - by) * inv);
        thi = fminf(thi, (lo - by) * inv);
    } else if (by <= lo || by >= hi) {
        thi = tlo - 1.0f;
    }
    k0 = max(0, (int)ceilf(tlo + 362.0f));
    k1 = min(NT - 1, (int)floorf(thi + 362.0f));
}

__device__ __forceinline__ void ray_setup(int v, int s, float& sn, float& c,
                                          float& bx, float& by, int& k0, int& k1) {
    float theta = (float)v * (float)(M_PI / (double)NVIEW);
    sincosf(theta, &sn, &c);
    float sf = (float)s - 367.5f;
    bx = fmaf(sf, c, 255.5f);
    by = fmaf(sf, sn, 255.5f);
    clip_ray(bx, by, sn, c, k0, k1);
}

// Deep-ILP tex integration: 8 outstanding TEX per thread, dual accumulator pairs.
template <int STRIDE>
__device__ __forceinline__ void integrate_tex(cudaTextureObject_t tex,
                                              int k0, int k1, int ti,
                                              float sn, float c, float bxu, float byu,
                                              float& accx, float& accy) {
    float a0x = 0.0f, a0y = 0.0f, a1x = 0.0f, a1y = 0.0f;
    int k = k0 + ti;
    float tf = (float)k - 362.0f;
    while (k <= k1) {
        #pragma unroll
        for (int u = 0; u < 8; ++u) {
            if (k <= k1) {
                float tfu = tf + (float)(u * STRIDE);
                float uu = fmaf(tfu, -sn, bxu);
                float wv = fmaf(tfu, c, byu);
                float2 val = tex2D<float2>(tex, uu, wv);
                if (u & 1) { a1x += val.x; a1y += val.y; }
                else       { a0x += val.x; a0y += val.y; }
            }
            k += STRIDE;
        }
        tf += (float)(8 * STRIDE);
    }
    accx = a0x + a1x;
    accy = a0y + a1y;
}

// Kernel A (tex): views |cos| >= sin. Warp: 8 det x 4 t-slots, quad = 2s x 2t.
// lane bits: b0=s lsb, b1=t parity, b2b3=s group, b4=t group.
__global__ void __launch_bounds__(256) radonTexA(cudaTextureObject_t tex,
                                                 float* __restrict__ out) {
    int lane = threadIdx.x & 31;
    int warp = threadIdx.x >> 5;
    int si = ((lane >> 2) & 3) * 2 + (lane & 1);
    int ti = ((lane >> 4) & 1) * 2 + ((lane >> 1) & 1);   // t-slot 0..3, stride 4
    int s = blockIdx.x * 64 + warp * 8 + si;
    int vy = blockIdx.y;
    int v = (vy < 193) ? vy : (vy + 383);
    if (s >= NDCT) return;  // warp-uniform

    float sn, c, bx, by;
    int k0, k1;
    ray_setup(v, s, sn, c, bx, by, k0, k1);

    float accx, accy;
    integrate_tex<4>(tex, k0, k1, ti, sn, c, bx + 0.5f, by + 0.5f, accx, accy);

    // reduce over t bits: b1 (xor 2) and b4 (xor 16)
    accx += __shfl_xor_sync(0xFFFFFFFFu, accx, 2);
    accy += __shfl_xor_sync(0xFFFFFFFFu, accy, 2);
    accx += __shfl_xor_sync(0xFFFFFFFFu, accx, 16);
    accy += __shfl_xor_sync(0xFFFFFFFFu, accy, 16);
    if ((lane & 18) == 0) {   // b1=b4=0
        out[v * NDCT + s] = accx;
        out[NVIEW * NDCT + v * NDCT + s] = accy;
    }
}

// Kernel B (tex): views sin > |cos|. Warp: 4 det x 8 t-slots, quad = 2s x 2t.
// lane bits: b0=s lsb, b1=t parity, b2=s group, b3b4=t group.
__global__ void __launch_bounds__(256) radonTexB(cudaTextureObject_t tex,
                                                 float* __restrict__ out) {
    int lane = threadIdx.x & 31;
    int warp = threadIdx.x >> 5;
    int si = ((lane >> 2) & 1) * 2 + (lane & 1);
    int ti = ((lane >> 3) & 3) * 2 + ((lane >> 1) & 1);   // t-slot 0..7, stride 8
    int s = blockIdx.x * 32 + warp * 4 + si;
    int v = 193 + blockIdx.y;

    float sn, c, bx, by;
    int k0, k1;
    ray_setup(v, s, sn, c, bx, by, k0, k1);

    float accx, accy;
    integrate_tex<8>(tex, k0, k1, ti, sn, c, bx + 0.5f, by + 0.5f, accx, accy);

    // reduce over t bits: b1 (2), b3 (8), b4 (16)
    accx += __shfl_xor_sync(0xFFFFFFFFu, accx, 2);
    accy += __shfl_xor_sync(0xFFFFFFFFu, accy, 2);
    accx += __shfl_xor_sync(0xFFFFFFFFu, accx, 8);
    accy += __shfl_xor_sync(0xFFFFFFFFu, accy, 8);
    accx += __shfl_xor_sync(0xFFFFFFFFu, accx, 16);
    accy += __shfl_xor_sync(0xFFFFFFFFu, accy, 16);
    if ((lane & 26) == 0) {   // b1=b3=b4=0
        out[v * NDCT + s] = accx;
        out[NVIEW * NDCT + v * NDCT + s] = accy;
    }
}

// ================= FALLBACK (R5 manual) =================
#define MAGIC 8388608.0f  // 2^23

__device__ __forceinline__ void sample_h(float xp, float yp, __half2& pacc) {
    float sx = __fadd_rd(xp, MAGIC);
    float sy = __fadd_rd(yp, MAGIC);
    int ixp = __float_as_int(sx) & 0x7FFFFF;
    int iyp = __float_as_int(sy) & 0x7FFFFF;
    float wx = xp - (sx - MAGIC);
    float wy = yp - (sy - MAGIC);
    __half2 wxh = __float2half2_rn(wx);
    __half2 wyh = __float2half2_rn(wy);
    int base = iyp * PW + ixp;
    HPair r0 = g_ph[base];
    HPair r1 = g_ph[base + PW];
    __half2 a0 = __hfma2(wxh, __hsub2(r0.hi, r0.lo), r0.lo);
    __half2 a1 = __hfma2(wxh, __hsub2(r1.hi, r1.lo), r1.lo);
    __half2 val = __hfma2(wyh, __hsub2(a1, a0), a0);
    pacc = __hadd2(pacc, val);
}

template <int STRIDE>
__device__ __forceinline__ void integrate(int k0, int k1, int ti,
                                          float sn, float c, float bxp, float byp,
                                          float& accx, float& accy) {
    int k = k0 + ti;
    float tf = (float)k - 362.0f;
    while (k <= k1) {
        __half2 pacc = __float2half2_rn(0.0f);
        #pragma unroll
        for (int u = 0; u < 8; ++u) {
            if (k <= k1) {
                float xp = fmaf(tf, -sn, bxp);
                float yp = fmaf(tf, c, byp);
                sample_h(xp, yp, pacc);
            }
            k += STRIDE;
            tf += (float)STRIDE;
        }
        float2 f = __half22float2(pacc);
        accx += f.x;
        accy += f.y;
    }
}

__global__ void __launch_bounds__(256) radonFbA(float* __restrict__ out) {
    int lane = threadIdx.x & 31, warp = threadIdx.x >> 5;
    int si = lane & 7, ti = lane >> 3;
    int s = blockIdx.x * 64 + warp * 8 + si;
    int vy = blockIdx.y;
    int v = (vy < 193) ? vy : (vy + 383);
    if (s >= NDCT) return;
    float sn, c, bx, byv; int k0, k1;
    ray_setup(v, s, sn, c, bx, byv, k0, k1);
    float accx = 0.0f, accy = 0.0f;
    integrate<4>(k0, k1, ti, sn, c, bx + 1.0f, byv + 1.0f, accx, accy);
    accx += __shfl_xor_sync(0xFFFFFFFFu, accx, 8);
    accy += __shfl_xor_sync(0xFFFFFFFFu, accy, 8);
    accx += __shfl_xor_sync(0xFFFFFFFFu, accx, 16);
    accy += __shfl_xor_sync(0xFFFFFFFFu, accy, 16);
    if (lane < 8) {
        out[v * NDCT + s] = accx;
        out[NVIEW * NDCT + v * NDCT + s] = accy;
    }
}
__global__ void __launch_bounds__(256) radonFbB(float* __restrict__ out) {
    int lane = threadIdx.x & 31, warp = threadIdx.x >> 5;
    int si = lane & 3, ti = lane >> 2;
    int s = blockIdx.x * 32 + warp * 4 + si;
    int v = 193 + blockIdx.y;
    float sn, c, bx, byv; int k0, k1;
    ray_setup(v, s, sn, c, bx, byv, k0, k1);
    float accx = 0.0f, accy = 0.0f;
    integrate<8>(k0, k1, ti, sn, c, bx + 1.0f, byv + 1.0f, accx, accy);
    accx += __shfl_xor_sync(0xFFFFFFFFu, accx, 4);
    accy += __shfl_xor_sync(0xFFFFFFFFu, accy, 4);
    accx += __shfl_xor_sync(0xFFFFFFFFu, accx, 8);
    accy += __shfl_xor_sync(0xFFFFFFFFu, accy, 8);
    accx += __shfl_xor_sync(0xFFFFFFFFu, accx, 16);
    accy += __shfl_xor_sync(0xFFFFFFFFu, accy, 16);
    if (lane < 4) {
        out[v * NDCT + s] = accx;
        out[NVIEW * NDCT + v * NDCT + s] = accy;
    }
}

// ---- one-time texture creation (first, uncaptured call only) ----
static int s_state = 0;                 // 0 untried, 1 tex ok, 2 fallback
static cudaTextureObject_t s_tex = 0;

static void init_tex_once() {
    if (s_state != 0) return;
    void* sym = nullptr;
    cudaError_t e = cudaGetSymbolAddress(&sym, g_himg);
    if (e == cudaSuccess) {
        cudaResourceDesc rd;
        memset(&rd, 0, sizeof(rd));
        rd.resType = cudaResourceTypePitch2D;
        rd.res.pitch2D.devPtr = sym;
        rd.res.pitch2D.desc = cudaCreateChannelDesc(16, 16, 0, 0, cudaChannelFormatKindFloat);
        rd.res.pitch2D.width = WW;
        rd.res.pitch2D.height = HH;
        rd.res.pitch2D.pitchInBytes = WW * sizeof(__half2);
        cudaTextureDesc td;
        memset(&td, 0, sizeof(td));
        td.addressMode[0] = cudaAddressModeBorder;
        td.addressMode[1] = cudaAddressModeBorder;
        td.filterMode = cudaFilterModeLinear;
        td.readMode = cudaReadModeElementType;
        td.normalizedCoords = 0;
        e = cudaCreateTextureObject(&s_tex, &rd, &td, nullptr);
        if (e == cudaSuccess) { s_state = 1; return; }
    }
    cudaGetLastError();
    s_state = 2;
}

extern "C" void kernel_launch(void* const* d_in, const int* in_sizes, int n_in,
                              void* d_out, int out_size) {
    const float* in = (const float*)d_in[0];
    float* out = (float*)d_out;

    init_tex_once();

    build_tables<<<(PH * PW + 255) / 256, 256>>>(in);

    if (s_state == 1) {
        dim3 gridA((NDCT + 63) / 64, 385);
        radonTexA<<<gridA, 256>>>(s_tex, out);
        dim3 gridB(NDCT / 32, 383);
        radonTexB<<<gridB, 256>>>(s_tex, out);
    } else {
        dim3 gridA((NDCT + 63) / 64, 385);
        radonFbA<<<gridA, 256>>>(out);
        dim3 gridB(NDCT / 32, 383);
        radonFbB<<<gridB, 256>>>(out);
    }
}

// round 15
// speedup vs baseline: 6.8517x; 1.0568x over previous
#include <cuda_runtime.h>
#include <cuda_fp16.h>
#include <math.h>
#include <string.h>

#define HH 512
#define WW 512
#define NVIEW 768
#define NDCT 736
#define NT 725

#define PW 513
#define PH 514

// texture image: half2 (ch0,ch1) per texel
__device__ __align__(512) __half2 g_himg[HH * WW];
// fallback pair table (manual path; built only if texture unavailable)
struct __align__(8) HPair { __half2 lo, hi; };
__device__ HPair g_ph[PH * PW];

__global__ void build_htex(const float* __restrict__ in) {
    int i = blockIdx.x * blockDim.x + threadIdx.x;
    if (i < HH * WW)
        g_himg[i] = __floats2half2_rn(in[i], in[HH * WW + i]);
}

__global__ void build_pair(const float* __restrict__ in) {
    int i = blockIdx.x * blockDim.x + threadIdx.x;
    if (i >= PH * PW) return;
    int py = i / PW;
    int px = i - py * PW;
    int y = py - 1;
    int x0 = px - 1;
    float l0 = 0.0f, l1 = 0.0f, h0 = 0.0f, h1 = 0.0f;
    if (y >= 0 && y < HH) {
        if (x0 >= 0) {
            l0 = in[y * WW + x0];
            l1 = in[HH * WW + y * WW + x0];
        }
        if (px < WW) {
            h0 = in[y * WW + px];
            h1 = in[HH * WW + y * WW + px];
        }
    }
    HPair p;
    p.lo = __floats2half2_rn(l0, l1);
    p.hi = __floats2half2_rn(h0, h1);
    g_ph[i] = p;
}

__device__ __forceinline__ void clip_ray(float bx, float by, float sn, float c,
                                         int& k0, int& k1) {
    float tlo = -362.0f, thi = 362.0f;
    const float lo = -0.999f;
    const float hi = 511.999f;
    if (sn > 1e-7f) {
        float inv = __frcp_rn(sn);
        tlo = fmaxf(tlo, (bx - hi) * inv);
        thi = fminf(thi, (bx - lo) * inv);
    } else if (bx <= lo || bx >= hi) {
        thi = tlo - 1.0f;
    }
    if (c > 1e-7f) {
        float inv = __frcp_rn(c);
        tlo = fmaxf(tlo, (lo - by) * inv);
        thi = fminf(thi, (hi - by) * inv);
    } else if (c < -1e-7f) {
        float inv = __frcp_rn(c);
        tlo = fmaxf(tlo, (hi - by) * inv);
        thi = fminf(thi, (lo - by) * inv);
    } else if (by <= lo || by >= hi) {
        thi = tlo - 1.0f;
    }
    k0 = max(0, (int)ceilf(tlo + 362.0f));
    k1 = min(NT - 1, (int)floorf(thi + 362.0f));
}

__device__ __forceinline__ void ray_setup(int v, int s, float& sn, float& c,
                                          float& bx, float& by, int& k0, int& k1) {
    float theta = (float)v * (float)(M_PI / (double)NVIEW);
    sincosf(theta, &sn, &c);
    float sf = (float)s - 367.5f;
    bx = fmaf(sf, c, 255.5f);
    by = fmaf(sf, sn, 255.5f);
    clip_ray(bx, by, sn, c, k0, k1);
}

// Deep-ILP tex integration: 8 outstanding TEX per thread, dual accumulator pairs.
template <int STRIDE>
__device__ __forceinline__ void integrate_tex(cudaTextureObject_t tex,
                                              int k0, int k1, int ti,
                                              float sn, float c, float bxu, float byu,
                                              float& accx, float& accy) {
    float a0x = 0.0f, a0y = 0.0f, a1x = 0.0f, a1y = 0.0f;
    int k = k0 + ti;
    float tf = (float)k - 362.0f;
    while (k <= k1) {
        #pragma unroll
        for (int u = 0; u < 8; ++u) {
            if (k <= k1) {
                float tfu = tf + (float)(u * STRIDE);
                float uu = fmaf(tfu, -sn, bxu);
                float wv = fmaf(tfu, c, byu);
                float2 val = tex2D<float2>(tex, uu, wv);
                if (u & 1) { a1x += val.x; a1y += val.y; }
                else       { a0x += val.x; a0y += val.y; }
            }
            k += STRIDE;
        }
        tf += (float)(8 * STRIDE);
    }
    accx = a0x + a1x;
    accy = a0y + a1y;
}

// Merged kernel, flat 1-D grid:
//   blocks [0, 4620):  A-class (|cos|>=sin). tile = b % 12, vy = b / 12.
//                      Warp: 8 det x 4 t-slots, quad = 2s x 2t.
//   blocks [4620, 13429): B-class. b' = b-4620; tile = b' % 23, vv = b' / 23.
//                      Warp: 4 det x 8 t-slots, quad = 2s x 2t.
#define NBLK_A 4620
#define NBLK_TOTAL 13429
__global__ void __launch_bounds__(256) radonTex(cudaTextureObject_t tex,
                                                float* __restrict__ out) {
    int lane = threadIdx.x & 31;
    int warp = threadIdx.x >> 5;
    int b = blockIdx.x;

    if (b < NBLK_A) {
        int tile = b % 12;
        int vy = b / 12;
        int v = (vy < 193) ? vy : (vy + 383);
        // lane bits: b0=s lsb, b1=t parity, b2b3=s group, b4=t group
        int si = ((lane >> 2) & 3) * 2 + (lane & 1);
        int ti = ((lane >> 4) & 1) * 2 + ((lane >> 1) & 1);   // 0..3, stride 4
        int s = tile * 64 + warp * 8 + si;
        if (s >= NDCT) return;  // warp-uniform

        float sn, c, bx, by;
        int k0, k1;
        ray_setup(v, s, sn, c, bx, by, k0, k1);

        float accx, accy;
        integrate_tex<4>(tex, k0, k1, ti, sn, c, bx + 0.5f, by + 0.5f, accx, accy);

        accx += __shfl_xor_sync(0xFFFFFFFFu, accx, 2);
        accy += __shfl_xor_sync(0xFFFFFFFFu, accy, 2);
        accx += __shfl_xor_sync(0xFFFFFFFFu, accx, 16);
        accy += __shfl_xor_sync(0xFFFFFFFFu, accy, 16);
        if ((lane & 18) == 0) {
            out[v * NDCT + s] = accx;
            out[NVIEW * NDCT + v * NDCT + s] = accy;
        }
    } else {
        int bb = b - NBLK_A;
        int tile = bb % 23;
        int v = 193 + bb / 23;
        // lane bits: b0=s lsb, b1=t parity, b2=s group, b3b4=t group
        int si = ((lane >> 2) & 1) * 2 + (lane & 1);
        int ti = ((lane >> 3) & 3) * 2 + ((lane >> 1) & 1);   // 0..7, stride 8
        int s = tile * 32 + warp * 4 + si;

        float sn, c, bx, by;
        int k0, k1;
        ray_setup(v, s, sn, c, bx, by, k0, k1);

        float accx, accy;
        integrate_tex<8>(tex, k0, k1, ti, sn, c, bx + 0.5f, by + 0.5f, accx, accy);

        accx += __shfl_xor_sync(0xFFFFFFFFu, accx, 2);
        accy += __shfl_xor_sync(0xFFFFFFFFu, accy, 2);
        accx += __shfl_xor_sync(0xFFFFFFFFu, accx, 8);
        accy += __shfl_xor_sync(0xFFFFFFFFu, accy, 8);
        accx += __shfl_xor_sync(0xFFFFFFFFu, accx, 16);
        accy += __shfl_xor_sync(0xFFFFFFFFu, accy, 16);
        if ((lane & 26) == 0) {
            out[v * NDCT + s] = accx;
            out[NVIEW * NDCT + v * NDCT + s] = accy;
        }
    }
}

// ================= FALLBACK (R5 manual) =================
#define MAGIC 8388608.0f  // 2^23

__device__ __forceinline__ void sample_h(float xp, float yp, __half2& pacc) {
    float sx = __fadd_rd(xp, MAGIC);
    float sy = __fadd_rd(yp, MAGIC);
    int ixp = __float_as_int(sx) & 0x7FFFFF;
    int iyp = __float_as_int(sy) & 0x7FFFFF;
    float wx = xp - (sx - MAGIC);
    float wy = yp - (sy - MAGIC);
    __half2 wxh = __float2half2_rn(wx);
    __half2 wyh = __float2half2_rn(wy);
    int base = iyp * PW + ixp;
    HPair r0 = g_ph[base];
    HPair r1 = g_ph[base + PW];
    __half2 a0 = __hfma2(wxh, __hsub2(r0.hi, r0.lo), r0.lo);
    __half2 a1 = __hfma2(wxh, __hsub2(r1.hi, r1.lo), r1.lo);
    __half2 val = __hfma2(wyh, __hsub2(a1, a0), a0);
    pacc = __hadd2(pacc, val);
}

template <int STRIDE>
__device__ __forceinline__ void integrate(int k0, int k1, int ti,
                                          float sn, float c, float bxp, float byp,
                                          float& accx, float& accy) {
    int k = k0 + ti;
    float tf = (float)k - 362.0f;
    while (k <= k1) {
        __half2 pacc = __float2half2_rn(0.0f);
        #pragma unroll
        for (int u = 0; u < 8; ++u) {
            if (k <= k1) {
                float xp = fmaf(tf, -sn, bxp);
                float yp = fmaf(tf, c, byp);
                sample_h(xp, yp, pacc);
            }
            k += STRIDE;
            tf += (float)STRIDE;
        }
        float2 f = __half22float2(pacc);
        accx += f.x;
        accy += f.y;
    }
}

__global__ void __launch_bounds__(256) radonFbA(float* __restrict__ out) {
    int lane = threadIdx.x & 31, warp = threadIdx.x >> 5;
    int si = lane & 7, ti = lane >> 3;
    int s = blockIdx.x * 64 + warp * 8 + si;
    int vy = blockIdx.y;
    int v = (vy < 193) ? vy : (vy + 383);
    if (s >= NDCT) return;
    float sn, c, bx, byv; int k0, k1;
    ray_setup(v, s, sn, c, bx, byv, k0, k1);
    float accx = 0.0f, accy = 0.0f;
    integrate<4>(k0, k1, ti, sn, c, bx + 1.0f, byv + 1.0f, accx, accy);
    accx += __shfl_xor_sync(0xFFFFFFFFu, accx, 8);
    accy += __shfl_xor_sync(0xFFFFFFFFu, accy, 8);
    accx += __shfl_xor_sync(0xFFFFFFFFu, accx, 16);
    accy += __shfl_xor_sync(0xFFFFFFFFu, accy, 16);
    if (lane < 8) {
        out[v * NDCT + s] = accx;
        out[NVIEW * NDCT + v * NDCT + s] = accy;
    }
}
__global__ void __launch_bounds__(256) radonFbB(float* __restrict__ out) {
    int lane = threadIdx.x & 31, warp = threadIdx.x >> 5;
    int si = lane & 3, ti = lane >> 2;
    int s = blockIdx.x * 32 + warp * 4 + si;
    int v = 193 + blockIdx.y;
    float sn, c, bx, byv; int k0, k1;
    ray_setup(v, s, sn, c, bx, byv, k0, k1);
    float accx = 0.0f, accy = 0.0f;
    integrate<8>(k0, k1, ti, sn, c, bx + 1.0f, byv + 1.0f, accx, accy);
    accx += __shfl_xor_sync(0xFFFFFFFFu, accx, 4);
    accy += __shfl_xor_sync(0xFFFFFFFFu, accy, 4);
    accx += __shfl_xor_sync(0xFFFFFFFFu, accx, 8);
    accy += __shfl_xor_sync(0xFFFFFFFFu, accy, 8);
    accx += __shfl_xor_sync(0xFFFFFFFFu, accx, 16);
    accy += __shfl_xor_sync(0xFFFFFFFFu, accy, 16);
    if (lane < 4) {
        out[v * NDCT + s] = accx;
        out[NVIEW * NDCT + v * NDCT + s] = accy;
    }
}

// ---- one-time texture creation (first, uncaptured call only) ----
static int s_state = 0;                 // 0 untried, 1 tex ok, 2 fallback
static cudaTextureObject_t s_tex = 0;

static void init_tex_once() {
    if (s_state != 0) return;
    void* sym = nullptr;
    cudaError_t e = cudaGetSymbolAddress(&sym, g_himg);
    if (e == cudaSuccess) {
        cudaResourceDesc rd;
        memset(&rd, 0, sizeof(rd));
        rd.resType = cudaResourceTypePitch2D;
        rd.res.pitch2D.devPtr = sym;
        rd.res.pitch2D.desc = cudaCreateChannelDesc(16, 16, 0, 0, cudaChannelFormatKindFloat);
        rd.res.pitch2D.width = WW;
        rd.res.pitch2D.height = HH;
        rd.res.pitch2D.pitchInBytes = WW * sizeof(__half2);
        cudaTextureDesc td;
        memset(&td, 0, sizeof(td));
        td.addressMode[0] = cudaAddressModeBorder;
        td.addressMode[1] = cudaAddressModeBorder;
        td.filterMode = cudaFilterModeLinear;
        td.readMode = cudaReadModeElementType;
        td.normalizedCoords = 0;
        e = cudaCreateTextureObject(&s_tex, &rd, &td, nullptr);
        if (e == cudaSuccess) { s_state = 1; return; }
    }
    cudaGetLastError();
    s_state = 2;
}

extern "C" void kernel_launch(void* const* d_in, const int* in_sizes, int n_in,
                              void* d_out, int out_size) {
    const float* in = (const float*)d_in[0];
    float* out = (float*)d_out;

    init_tex_once();

    if (s_state == 1) {
        build_htex<<<(HH * WW + 255) / 256, 256>>>(in);
        radonTex<<<NBLK_TOTAL, 256>>>(s_tex, out);
    } else {
        build_pair<<<(PH * PW + 255) / 256, 256>>>(in);
        dim3 gridA((NDCT + 63) / 64, 385);
        radonFbA<<<gridA, 256>>>(out);
        dim3 gridB(NDCT / 32, 383);
        radonFbB<<<gridB, 256>>>(out);
    }
}